// round 3
// baseline (speedup 1.0000x reference)
#include <cuda_runtime.h>
#include <cuda_bf16.h>
#include <cstdint>
#include <math.h>

#define TT 512
#define BB 128
#define II 256
#define HH 1024
#define G4 (4 * HH)
#define K3 (3 * HH)          // 3072: [hi | hi | lo] x [Whi | Wlo | Whi]
#define NBLK 64              // N columns per block
#define NBLOCKS (G4 / NBLK)  // 64 blocks
#define KCH 64               // k elements per smem chunk
#define NCHUNKS (K3 / KCH)   // 48
#define KSTR 72              // padded smem row stride (bf16 elems) = 144B
#define ABYTES (128 * KSTR * 2)              // 18432
#define BBYTES (NBLK * KSTR * 2)             // 9216
#define BUFBYTES (ABYTES + BBYTES)           // 27648
#define SMEM_TOTAL (2 * BUFBYTES)            // 55296

// ---------------- scratch (__device__ globals; allocation-free) -------------
__device__ float g_xproj[(size_t)TT * BB * G4];            // permuted cols
__device__ float g_c[BB * HH];
__device__ __nv_bfloat16 g_hsplit[BB * K3];                // [b][3072]
__device__ __nv_bfloat16 g_Wsplit[(size_t)G4 * K3];        // [perm row][3072]

// ======================= helpers =============================================
__device__ __forceinline__ uint32_t smem_to_u32(const void* p) {
    uint32_t a;
    asm("{ .reg .u64 t; cvta.to.shared.u64 t, %1; cvt.u32.u64 %0, t; }"
        : "=r"(a) : "l"(p));
    return a;
}
__device__ __forceinline__ void cp_async16(uint32_t dst, const void* src) {
    size_t gsrc = __cvta_generic_to_global(src);
    asm volatile("cp.async.cg.shared.global [%0], [%1], 16;"
                 :: "r"(dst), "l"(gsrc) : "memory");
}
__device__ __forceinline__ void cp_commit() {
    asm volatile("cp.async.commit_group;" ::: "memory");
}
__device__ __forceinline__ void cp_wait1() {
    asm volatile("cp.async.wait_group 1;" ::: "memory");
}
__device__ __forceinline__ void cp_wait0() {
    asm volatile("cp.async.wait_group 0;" ::: "memory");
}
__device__ __forceinline__ void ldm_x4(uint32_t* r, uint32_t addr) {
    asm volatile("ldmatrix.sync.aligned.m8n8.x4.shared.b16 {%0,%1,%2,%3}, [%4];"
                 : "=r"(r[0]), "=r"(r[1]), "=r"(r[2]), "=r"(r[3]) : "r"(addr));
}
__device__ __forceinline__ void mma_bf16(float* d, const uint32_t* a,
                                         uint32_t b0, uint32_t b1) {
    asm volatile(
        "mma.sync.aligned.m16n8k16.row.col.f32.bf16.bf16.f32 "
        "{%0,%1,%2,%3}, {%4,%5,%6,%7}, {%8,%9}, {%0,%1,%2,%3};"
        : "+f"(d[0]), "+f"(d[1]), "+f"(d[2]), "+f"(d[3])
        : "r"(a[0]), "r"(a[1]), "r"(a[2]), "r"(a[3]), "r"(b0), "r"(b1));
}
__device__ __forceinline__ float sigf(float x) { return 1.0f / (1.0f + expf(-x)); }

// ======================= init kernels =======================================
__global__ void init_state(const float* __restrict__ h0, const float* __restrict__ c0) {
    int i = blockIdx.x * blockDim.x + threadIdx.x;
    if (i < BB * HH) {
        g_c[i] = c0[i];
        float h = h0[i];
        __nv_bfloat16 hi = __float2bfloat16(h);
        __nv_bfloat16 lo = __float2bfloat16(h - __bfloat162float(hi));
        int b = i / HH, k = i % HH;
        g_hsplit[(size_t)b * K3 + k] = hi;
        g_hsplit[(size_t)b * K3 + HH + k] = hi;
        g_hsplit[(size_t)b * K3 + 2 * HH + k] = lo;
    }
}

__global__ void wsplit_kernel(const float* __restrict__ W) {
    size_t i = (size_t)blockIdx.x * blockDim.x + threadIdx.x;
    if (i < (size_t)G4 * HH) {
        int n = (int)(i / HH), k = (int)(i % HH);
        float w = W[i];
        __nv_bfloat16 hi = __float2bfloat16(w);
        __nv_bfloat16 lo = __float2bfloat16(w - __bfloat162float(hi));
        int r = ((n & 1023) << 2) | (n >> 10);   // interleave gates per hcol
        g_Wsplit[(size_t)r * K3 + k] = hi;
        g_Wsplit[(size_t)r * K3 + HH + k] = lo;
        g_Wsplit[(size_t)r * K3 + 2 * HH + k] = hi;
    }
}

// ======================= xproj GEMM (fp32, permuted output) =================
__global__ __launch_bounds__(256) void xproj_kernel(
    const float* __restrict__ inp, const float* __restrict__ W_ih,
    const float* __restrict__ b_ih, const float* __restrict__ b_hh)
{
    __shared__ float As[32][64];
    __shared__ float Bs[32][64];
    const int tid = threadIdx.x;
    const int tx = tid & 15, ty = tid >> 4;
    const int n0 = blockIdx.x * 64, m0 = blockIdx.y * 64;

    float acc[4][4];
#pragma unroll
    for (int r = 0; r < 4; r++)
#pragma unroll
        for (int c = 0; c < 4; c++) acc[r][c] = 0.f;

    for (int k0 = 0; k0 < II; k0 += 32) {
#pragma unroll
        for (int v = 0; v < 2; v++) {
            int e = tid + 256 * v;
            int row = e >> 3, kk = (e & 7) * 4;
            float4 a = *(const float4*)(inp + (size_t)(m0 + row) * II + k0 + kk);
            As[kk + 0][row] = a.x; As[kk + 1][row] = a.y;
            As[kk + 2][row] = a.z; As[kk + 3][row] = a.w;
            float4 b = *(const float4*)(W_ih + (size_t)(n0 + row) * II + k0 + kk);
            Bs[kk + 0][row] = b.x; Bs[kk + 1][row] = b.y;
            Bs[kk + 2][row] = b.z; Bs[kk + 3][row] = b.w;
        }
        __syncthreads();
#pragma unroll
        for (int kk = 0; kk < 32; kk++) {
            float4 av = *(const float4*)(&As[kk][ty * 4]);
            float4 bv = *(const float4*)(&Bs[kk][tx * 4]);
            float a4[4] = {av.x, av.y, av.z, av.w};
            float b4[4] = {bv.x, bv.y, bv.z, bv.w};
#pragma unroll
            for (int r = 0; r < 4; r++)
#pragma unroll
                for (int c = 0; c < 4; c++) acc[r][c] += a4[r] * b4[c];
        }
        __syncthreads();
    }
#pragma unroll
    for (int c = 0; c < 4; c++) {
        int n = n0 + tx * 4 + c;
        float bias = b_ih[n] + b_hh[n];
        int pn = ((n & 1023) << 2) | (n >> 10);
#pragma unroll
        for (int r = 0; r < 4; r++) {
            int m = m0 + ty * 4 + r;
            g_xproj[(size_t)m * G4 + pn] = acc[r][c] + bias;
        }
    }
}

// ======================= HMMA LSTM step ======================================
// grid 64, block 256 (8 warps: 4 along M x 2 along N). Block computes
// gates[128, 64] = A'[128,3072] @ B'[64,3072]^T with fp32 accum, then the
// fused LSTM cell update (gate-interleaved columns: col = 4*hcol + gate).
__global__ __launch_bounds__(256) void lstm_step_mma(float* __restrict__ out, int t)
{
    extern __shared__ __align__(16) char smem[];
    const uint32_t smem_base = smem_to_u32(smem);
    const int tid = threadIdx.x;
    const int wid = tid >> 5, lane = tid & 31;
    const int n0 = blockIdx.x * NBLK;
    const int warp_m = (wid & 3) * 32;
    const int warp_n = (wid >> 2) * 32;

    float acc[2][4][4];
#pragma unroll
    for (int mi = 0; mi < 2; mi++)
#pragma unroll
        for (int ni = 0; ni < 4; ni++)
#pragma unroll
            for (int v = 0; v < 4; v++) acc[mi][ni][v] = 0.f;

    // -------- async copy of one k-chunk into buffer `buf` --------
    auto issue = [&](int j, int buf) {
        if (j < NCHUNKS) {
            const int k0 = j * KCH;
            const uint32_t base = smem_base + buf * BUFBYTES;
#pragma unroll
            for (int i = 0; i < 6; i++) {
                int idx = tid + (i << 8);
                if (idx < 1024) {
                    int row = idx >> 3, c = idx & 7;
                    cp_async16(base + row * (KSTR * 2) + (c << 4),
                               g_hsplit + (size_t)row * K3 + k0 + (c << 3));
                } else {
                    int x = idx - 1024;
                    int row = x >> 3, c = x & 7;
                    cp_async16(base + ABYTES + row * (KSTR * 2) + (c << 4),
                               g_Wsplit + (size_t)(n0 + row) * K3 + k0 + (c << 3));
                }
            }
        }
        cp_commit();
    };

    issue(0, 0);
    issue(1, 1);

    for (int j = 0; j < NCHUNKS; j++) {
        const int buf = j & 1;
        cp_wait1();
        __syncthreads();

        const uint32_t aBase = smem_base + buf * BUFBYTES;
        const uint32_t bBase = aBase + ABYTES;
        const uint32_t aRow = aBase + (warp_m + (lane & 15)) * (KSTR * 2)
                                    + (lane >> 4) * 16;
#pragma unroll
        for (int ks = 0; ks < 4; ks++) {
            const int kb = ks * 16;
            uint32_t a[2][4];
#pragma unroll
            for (int mi = 0; mi < 2; mi++)
                ldm_x4(a[mi], aRow + mi * 16 * (KSTR * 2) + kb * 2);
            uint32_t b[2][4];
#pragma unroll
            for (int nb = 0; nb < 2; nb++) {
                uint32_t addr = bBase
                    + (warp_n + nb * 16 + (lane & 15)) * (KSTR * 2)
                    + kb * 2 + (lane >> 4) * 16;
                ldm_x4(b[nb], addr);
            }
#pragma unroll
            for (int mi = 0; mi < 2; mi++)
#pragma unroll
                for (int ni = 0; ni < 4; ni++) {
                    int nb = ni >> 1, sub = ni & 1;
                    mma_bf16(acc[mi][ni], a[mi], b[nb][sub], b[nb][sub + 2]);
                }
        }
        __syncthreads();
        issue(j + 2, buf);
    }
    cp_wait0();

    // ---------- fused LSTM cell epilogue -----------------------------------
    // thread t owns output rows (warp_m + mi*16 + q, +8), cols 2*(t%4)+{0,1}
    // per 8-col n-tile. Lane pairs (r4 even, odd) hold (i,f) / (g,o) of one
    // hcol; exchange via shfl, even lane does the cell update.
    const int q = lane >> 2, r4 = lane & 3;
    const bool writer = (r4 & 1) == 0;
    const int hl = r4 >> 1;
    const float* xpb = g_xproj + (size_t)t * BB * G4;
    const size_t OUT_H = (size_t)TT * BB * HH;

#pragma unroll
    for (int mi = 0; mi < 2; mi++)
#pragma unroll
        for (int ni = 0; ni < 4; ni++)
#pragma unroll
            for (int h = 0; h < 2; h++) {
                float v0 = acc[mi][ni][2 * h];
                float v1 = acc[mi][ni][2 * h + 1];
                float p0 = __shfl_xor_sync(0xffffffffu, v0, 1);
                float p1 = __shfl_xor_sync(0xffffffffu, v1, 1);
                if (writer) {
                    int m = warp_m + mi * 16 + h * 8 + q;
                    int nl = warp_n + ni * 8 + hl * 4;
                    int hc = (n0 + nl) >> 2;
                    float4 xv = *(const float4*)(xpb + (size_t)m * G4 + n0 + nl);
                    float ig = sigf(v0 + xv.x);
                    float fg = sigf(v1 + xv.y);
                    float gg = tanhf(p0 + xv.z);
                    float og = sigf(p1 + xv.w);
                    size_t cidx = (size_t)m * HH + hc;
                    float cn = fg * g_c[cidx] + ig * gg;
                    g_c[cidx] = cn;
                    float hn = og * tanhf(cn);
                    out[(size_t)t * BB * HH + cidx] = hn;
                    __nv_bfloat16 hi = __float2bfloat16(hn);
                    __nv_bfloat16 lo = __float2bfloat16(hn - __bfloat162float(hi));
                    g_hsplit[(size_t)m * K3 + hc] = hi;
                    g_hsplit[(size_t)m * K3 + HH + hc] = hi;
                    g_hsplit[(size_t)m * K3 + 2 * HH + hc] = lo;
                    if (t == TT - 1) {
                        out[OUT_H + cidx] = hn;
                        out[OUT_H + (size_t)BB * HH + cidx] = cn;
                    }
                }
            }
}

// ============================================================================
extern "C" void kernel_launch(void* const* d_in, const int* in_sizes, int n_in,
                              void* d_out, int out_size) {
    const float* inputs = (const float*)d_in[0];  // [512,128,256]
    const float* h0     = (const float*)d_in[1];
    const float* c0     = (const float*)d_in[2];
    const float* W_ih   = (const float*)d_in[3];  // [4096,256]
    const float* W_hh   = (const float*)d_in[4];  // [4096,1024]
    const float* b_ih   = (const float*)d_in[5];
    const float* b_hh   = (const float*)d_in[6];
    float* out = (float*)d_out;

    cudaFuncSetAttribute(lstm_step_mma,
                         cudaFuncAttributeMaxDynamicSharedMemorySize, SMEM_TOTAL);

    init_state<<<(BB * HH + 255) / 256, 256>>>(h0, c0);
    wsplit_kernel<<<(int)(((size_t)G4 * HH + 255) / 256), 256>>>(W_hh);

    dim3 xgrid(G4 / 64, (TT * BB) / 64);
    xproj_kernel<<<xgrid, 256>>>(inputs, W_ih, b_ih, b_hh);

    for (int t = 0; t < TT; t++) {
        lstm_step_mma<<<NBLOCKS, 256, SMEM_TOTAL>>>(out, t);
    }
}

// round 5
// speedup vs baseline: 2.0875x; 2.0875x over previous
#include <cuda_runtime.h>
#include <cuda_bf16.h>
#include <cstdint>
#include <math.h>

#define TT 512
#define BB 128
#define II 256
#define HH 1024
#define G4 (4 * HH)
#define K2 2048               // [hi(1024) | lo(1024)]
#define NBLK 32               // gate-cols per block
#define GRIDN 128             // persistent blocks (<=148 SMs, 1 CTA/SM)
#define KCH 32                // k per pipeline stage
#define NCH (HH / KCH)        // 32 chunks per step
#define STRW_E 2056           // W smem row stride (elems)
#define STRW_B (STRW_E * 2)   // 4112 B
#define STRA_B 80             // A smem row stride (bytes), 32 elems + pad
#define W_BYTES (NBLK * STRW_B)          // 131584
#define AHI_B (128 * STRA_B)             // 10240
#define STG_B (2 * AHI_B)                // 20480 (hi+lo)
#define NSTAGE 4
#define SMEM_TOTAL (W_BYTES + NSTAGE * STG_B)  // 213504

// ---------------- scratch (__device__ globals; allocation-free) -------------
__device__ float g_xproj[(size_t)TT * BB * G4];        // permuted gate cols
__device__ float g_c[BB * HH];
__device__ __nv_bfloat16 g_hsplit[2][BB * K2];         // double-buffered h
__device__ __nv_bfloat16 g_Wsplit[(size_t)G4 * K2];    // [perm row][hi|lo]
__device__ unsigned g_bar[TT];                          // per-step barrier

// ======================= helpers =============================================
__device__ __forceinline__ uint32_t smem_to_u32(const void* p) {
    uint32_t a;
    asm("{ .reg .u64 t; cvta.to.shared.u64 t, %1; cvt.u32.u64 %0, t; }"
        : "=r"(a) : "l"(p));
    return a;
}
__device__ __forceinline__ void cp_async16(uint32_t dst, const void* src) {
    size_t gsrc = __cvta_generic_to_global(src);
    asm volatile("cp.async.cg.shared.global [%0], [%1], 16;"
                 :: "r"(dst), "l"(gsrc) : "memory");
}
__device__ __forceinline__ void cp_commit() {
    asm volatile("cp.async.commit_group;" ::: "memory");
}
__device__ __forceinline__ void ldm_x4(uint32_t* r, uint32_t addr) {
    asm volatile("ldmatrix.sync.aligned.m8n8.x4.shared.b16 {%0,%1,%2,%3}, [%4];"
                 : "=r"(r[0]), "=r"(r[1]), "=r"(r[2]), "=r"(r[3]) : "r"(addr));
}
__device__ __forceinline__ void mma_bf16(float* d, const uint32_t* a,
                                         uint32_t b0, uint32_t b1) {
    asm volatile(
        "mma.sync.aligned.m16n8k16.row.col.f32.bf16.bf16.f32 "
        "{%0,%1,%2,%3}, {%4,%5,%6,%7}, {%8,%9}, {%0,%1,%2,%3};"
        : "+f"(d[0]), "+f"(d[1]), "+f"(d[2]), "+f"(d[3])
        : "r"(a[0]), "r"(a[1]), "r"(a[2]), "r"(a[3]), "r"(b0), "r"(b1));
}
__device__ __forceinline__ float sigf(float x) { return 1.0f / (1.0f + expf(-x)); }

// ======================= init kernels =======================================
__global__ void init_state(const float* __restrict__ h0, const float* __restrict__ c0) {
    int i = blockIdx.x * blockDim.x + threadIdx.x;
    if (i < BB * HH) {
        g_c[i] = c0[i];
        float h = h0[i];
        __nv_bfloat16 hi = __float2bfloat16(h);
        __nv_bfloat16 lo = __float2bfloat16(h - __bfloat162float(hi));
        int b = i / HH, k = i % HH;
        g_hsplit[0][(size_t)b * K2 + k] = hi;
        g_hsplit[0][(size_t)b * K2 + HH + k] = lo;
    }
    if (i < TT) g_bar[i] = 0u;
}

__global__ void wsplit_kernel(const float* __restrict__ W) {
    size_t i = (size_t)blockIdx.x * blockDim.x + threadIdx.x;
    if (i < (size_t)G4 * HH) {
        int n = (int)(i / HH), k = (int)(i % HH);
        float w = W[i];
        __nv_bfloat16 hi = __float2bfloat16(w);
        __nv_bfloat16 lo = __float2bfloat16(w - __bfloat162float(hi));
        int r = ((n & 1023) << 2) | (n >> 10);   // gate-interleaved perm
        g_Wsplit[(size_t)r * K2 + k] = hi;
        g_Wsplit[(size_t)r * K2 + HH + k] = lo;
    }
}

// ======================= xproj GEMM (fp32, permuted output) =================
__global__ __launch_bounds__(256) void xproj_kernel(
    const float* __restrict__ inp, const float* __restrict__ W_ih,
    const float* __restrict__ b_ih, const float* __restrict__ b_hh)
{
    __shared__ float As[32][64];
    __shared__ float Bs[32][64];
    const int tid = threadIdx.x;
    const int tx = tid & 15, ty = tid >> 4;
    const int n0 = blockIdx.x * 64, m0 = blockIdx.y * 64;

    float acc[4][4];
#pragma unroll
    for (int r = 0; r < 4; r++)
#pragma unroll
        for (int c = 0; c < 4; c++) acc[r][c] = 0.f;

    for (int k0 = 0; k0 < II; k0 += 32) {
#pragma unroll
        for (int v = 0; v < 2; v++) {
            int e = tid + 256 * v;
            int row = e >> 3, kk = (e & 7) * 4;
            float4 a = *(const float4*)(inp + (size_t)(m0 + row) * II + k0 + kk);
            As[kk + 0][row] = a.x; As[kk + 1][row] = a.y;
            As[kk + 2][row] = a.z; As[kk + 3][row] = a.w;
            float4 b = *(const float4*)(W_ih + (size_t)(n0 + row) * II + k0 + kk);
            Bs[kk + 0][row] = b.x; Bs[kk + 1][row] = b.y;
            Bs[kk + 2][row] = b.z; Bs[kk + 3][row] = b.w;
        }
        __syncthreads();
#pragma unroll
        for (int kk = 0; kk < 32; kk++) {
            float4 av = *(const float4*)(&As[kk][ty * 4]);
            float4 bv = *(const float4*)(&Bs[kk][tx * 4]);
            float a4[4] = {av.x, av.y, av.z, av.w};
            float b4[4] = {bv.x, bv.y, bv.z, bv.w};
#pragma unroll
            for (int r = 0; r < 4; r++)
#pragma unroll
                for (int c = 0; c < 4; c++) acc[r][c] += a4[r] * b4[c];
        }
        __syncthreads();
    }
#pragma unroll
    for (int c = 0; c < 4; c++) {
        int n = n0 + tx * 4 + c;
        float bias = b_ih[n] + b_hh[n];
        int pn = ((n & 1023) << 2) | (n >> 10);
#pragma unroll
        for (int r = 0; r < 4; r++) {
            int m = m0 + ty * 4 + r;
            g_xproj[(size_t)m * G4 + pn] = acc[r][c] + bias;
        }
    }
}

// ======================= persistent LSTM kernel =============================
// grid 128, block 256 (8 warps = 4(M) x 2(N)). Block owns 32 permuted gate
// cols (8 hcols) with its W slice resident in smem for all 512 steps.
__global__ __launch_bounds__(256, 1) void lstm_persistent(float* __restrict__ out)
{
    extern __shared__ __align__(16) char smem[];
    const uint32_t sb = smem_to_u32(smem);
    const int tid = threadIdx.x;
    const int wid = tid >> 5, lane = tid & 31;
    const int n0g = blockIdx.x * NBLK;
    const int warp_m = (wid & 3) * 32;
    const int warp_n = (wid >> 2) * 16;

    // ---- load W slice (32 rows x 2048 bf16 = 32 x 256 x 16B) into smem ----
    for (int i = tid; i < 8192; i += 256) {
        int row = i >> 8, gr = i & 255;       // FIXED: 256 16B-groups per row
        cp_async16(sb + row * STRW_B + gr * 16,
                   g_Wsplit + (size_t)(n0g + row) * K2 + gr * 8);
    }
    cp_commit();
    asm volatile("cp.async.wait_group 0;" ::: "memory");
    __syncthreads();

    const uint32_t stg0 = sb + W_BYTES;
    const size_t OUT_H = (size_t)TT * BB * HH;
    const int q = lane >> 2, r4 = lane & 3;
    const bool writer = (r4 & 1) == 0;
    const int hl = r4 >> 1;

    for (int t = 0; t < TT; t++) {
        const int rb = t & 1, wb = rb ^ 1;
        const __nv_bfloat16* hbase = g_hsplit[rb];

        auto issueA = [&](int j) {
            if (j < NCH) {
                const int k0 = j * KCH;
                const uint32_t st = stg0 + (j & 3) * STG_B;
#pragma unroll
                for (int i = 0; i < 4; i++) {
                    int idx = tid + (i << 8);       // 0..1023
                    int half = idx >> 9;            // 0: hi, 1: lo
                    int x = idx & 511;
                    int row = x & 127, gr = x >> 7; // 4 x 16B = 32 elems/row
                    cp_async16(st + half * AHI_B + row * STRA_B + gr * 16,
                               hbase + (size_t)row * K2 + half * HH + k0 + gr * 8);
                }
            }
            cp_commit();
        };

        float acc[2][2][4];
#pragma unroll
        for (int mi = 0; mi < 2; mi++)
#pragma unroll
            for (int ni = 0; ni < 2; ni++)
#pragma unroll
                for (int v = 0; v < 4; v++) acc[mi][ni][v] = 0.f;

        issueA(0); issueA(1); issueA(2);

        for (int j = 0; j < NCH; j++) {
            asm volatile("cp.async.wait_group 2;" ::: "memory");
            __syncthreads();
            issueA(j + 3);                    // overwrites stage of chunk j-1
            const uint32_t st = stg0 + (j & 3) * STG_B;
            const int k0 = j * KCH;
#pragma unroll
            for (int ks = 0; ks < 2; ks++) {
                uint32_t ahi[2][4], alo[2][4], bhi[4], blo[4];
                const uint32_t arow = st + (warp_m + (lane & 15)) * STRA_B
                                        + ks * 32 + (lane >> 4) * 16;
                ldm_x4(ahi[0], arow);
                ldm_x4(ahi[1], arow + 16 * STRA_B);
                ldm_x4(alo[0], arow + AHI_B);
                ldm_x4(alo[1], arow + AHI_B + 16 * STRA_B);
                const uint32_t brow = sb + (warp_n + (lane & 15)) * STRW_B
                                        + (k0 + ks * 16) * 2 + (lane >> 4) * 16;
                ldm_x4(bhi, brow);
                ldm_x4(blo, brow + HH * 2);
#pragma unroll
                for (int mi = 0; mi < 2; mi++)
#pragma unroll
                    for (int ni = 0; ni < 2; ni++) {
                        mma_bf16(acc[mi][ni], ahi[mi], bhi[ni], bhi[ni + 2]);
                        mma_bf16(acc[mi][ni], ahi[mi], blo[ni], blo[ni + 2]);
                        mma_bf16(acc[mi][ni], alo[mi], bhi[ni], bhi[ni + 2]);
                    }
            }
        }

        // ---------- fused LSTM cell epilogue ------------------------------
        const float* xpb = g_xproj + (size_t)t * BB * G4;
        __nv_bfloat16* hw = g_hsplit[wb];
#pragma unroll
        for (int mi = 0; mi < 2; mi++)
#pragma unroll
            for (int ni = 0; ni < 2; ni++)
#pragma unroll
                for (int h = 0; h < 2; h++) {
                    float v0 = acc[mi][ni][2 * h];
                    float v1 = acc[mi][ni][2 * h + 1];
                    float p0 = __shfl_xor_sync(0xffffffffu, v0, 1);
                    float p1 = __shfl_xor_sync(0xffffffffu, v1, 1);
                    if (writer) {
                        int m = warp_m + mi * 16 + h * 8 + q;
                        int col = n0g + warp_n + ni * 8 + hl * 4;
                        int hc = col >> 2;
                        float4 xv = *(const float4*)(xpb + (size_t)m * G4 + col);
                        float ig = sigf(v0 + xv.x);
                        float fg = sigf(v1 + xv.y);
                        float gg = tanhf(p0 + xv.z);
                        float og = sigf(p1 + xv.w);
                        size_t cidx = (size_t)m * HH + hc;
                        float cn = fg * g_c[cidx] + ig * gg;
                        g_c[cidx] = cn;
                        float hn = og * tanhf(cn);
                        out[(size_t)t * BB * HH + cidx] = hn;
                        __nv_bfloat16 hi = __float2bfloat16(hn);
                        __nv_bfloat16 lo =
                            __float2bfloat16(hn - __bfloat162float(hi));
                        hw[(size_t)m * K2 + hc] = hi;
                        hw[(size_t)m * K2 + HH + hc] = lo;
                        if (t == TT - 1) {
                            out[OUT_H + cidx] = hn;
                            out[OUT_H + (size_t)BB * HH + cidx] = cn;
                        }
                    }
                }

        // ---------- grid-wide barrier (all blocks resident) ---------------
        if (t < TT - 1) {
            __syncthreads();
            if (tid == 0) {
                unsigned* bar = &g_bar[t];
                asm volatile("red.release.gpu.global.add.u32 [%0], 1;"
                             :: "l"(bar) : "memory");
                unsigned v;
                do {
                    asm volatile("ld.acquire.gpu.global.u32 %0, [%1];"
                                 : "=r"(v) : "l"(bar));
                } while (v < GRIDN);
            }
            __syncthreads();
        }
    }
}

// ============================================================================
extern "C" void kernel_launch(void* const* d_in, const int* in_sizes, int n_in,
                              void* d_out, int out_size) {
    const float* inputs = (const float*)d_in[0];  // [512,128,256]
    const float* h0     = (const float*)d_in[1];
    const float* c0     = (const float*)d_in[2];
    const float* W_ih   = (const float*)d_in[3];  // [4096,256]
    const float* W_hh   = (const float*)d_in[4];  // [4096,1024]
    const float* b_ih   = (const float*)d_in[5];
    const float* b_hh   = (const float*)d_in[6];
    float* out = (float*)d_out;

    cudaFuncSetAttribute(lstm_persistent,
                         cudaFuncAttributeMaxDynamicSharedMemorySize, SMEM_TOTAL);

    init_state<<<(BB * HH + 255) / 256, 256>>>(h0, c0);
    wsplit_kernel<<<(int)(((size_t)G4 * HH + 255) / 256), 256>>>(W_hh);

    dim3 xgrid(G4 / 64, (TT * BB) / 64);
    xproj_kernel<<<xgrid, 256>>>(inputs, W_ih, b_ih, b_hh);

    lstm_persistent<<<GRIDN, 256, SMEM_TOTAL>>>(out);
}

// round 6
// speedup vs baseline: 2.1847x; 1.0465x over previous
#include <cuda_runtime.h>
#include <cuda_bf16.h>
#include <cstdint>
#include <math.h>

#define TT 512
#define BB 128
#define II 256
#define HH 1024
#define G4 (4 * HH)
#define K2 2048               // [hi(1024) | lo(1024)]
#define NBLK 32               // gate-cols per block
#define GRIDN 128             // persistent blocks (<=148 SMs, 1 CTA/SM)
#define NTHR 512              // 16 warps: 4(M) x 2(N) x 2(K-split)
#define KCH 32                // k per pipeline stage (2 k16-units)
#define NCH (HH / KCH)        // 32 chunks per step
#define STRW_E 2056           // W smem row stride (elems)
#define STRW_B (STRW_E * 2)   // 4112 B
#define STRA_B 80             // A smem row stride (bytes), 32 elems + pad
#define W_BYTES (NBLK * STRW_B)          // 131584
#define AHI_B (128 * STRA_B)             // 10240
#define STG_B (2 * AHI_B)                // 20480 (hi+lo)
#define NSTAGE 4
#define SMEM_TOTAL (W_BYTES + NSTAGE * STG_B)  // 213504

// ---------------- scratch (__device__ globals; allocation-free) -------------
__device__ float g_xproj[(size_t)TT * BB * G4];        // permuted gate cols
__device__ float g_c[BB * HH];
__device__ __nv_bfloat16 g_hsplit[2][BB * K2];         // double-buffered h
__device__ __nv_bfloat16 g_Wsplit[(size_t)G4 * K2];    // [perm row][hi|lo]
__device__ unsigned g_bar[TT];                          // per-step barrier

// ======================= helpers =============================================
__device__ __forceinline__ uint32_t smem_to_u32(const void* p) {
    uint32_t a;
    asm("{ .reg .u64 t; cvta.to.shared.u64 t, %1; cvt.u32.u64 %0, t; }"
        : "=r"(a) : "l"(p));
    return a;
}
__device__ __forceinline__ void cp_async16(uint32_t dst, const void* src) {
    size_t gsrc = __cvta_generic_to_global(src);
    asm volatile("cp.async.cg.shared.global [%0], [%1], 16;"
                 :: "r"(dst), "l"(gsrc) : "memory");
}
__device__ __forceinline__ void cp_commit() {
    asm volatile("cp.async.commit_group;" ::: "memory");
}
__device__ __forceinline__ void ldm_x4(uint32_t* r, uint32_t addr) {
    asm volatile("ldmatrix.sync.aligned.m8n8.x4.shared.b16 {%0,%1,%2,%3}, [%4];"
                 : "=r"(r[0]), "=r"(r[1]), "=r"(r[2]), "=r"(r[3]) : "r"(addr));
}
__device__ __forceinline__ void mma_bf16(float* d, const uint32_t* a,
                                         uint32_t b0, uint32_t b1) {
    asm volatile(
        "mma.sync.aligned.m16n8k16.row.col.f32.bf16.bf16.f32 "
        "{%0,%1,%2,%3}, {%4,%5,%6,%7}, {%8,%9}, {%0,%1,%2,%3};"
        : "+f"(d[0]), "+f"(d[1]), "+f"(d[2]), "+f"(d[3])
        : "r"(a[0]), "r"(a[1]), "r"(a[2]), "r"(a[3]), "r"(b0), "r"(b1));
}
__device__ __forceinline__ float sigf(float x) { return 1.0f / (1.0f + expf(-x)); }

// ======================= init kernels =======================================
__global__ void init_state(const float* __restrict__ h0, const float* __restrict__ c0) {
    int i = blockIdx.x * blockDim.x + threadIdx.x;
    if (i < BB * HH) {
        g_c[i] = c0[i];
        float h = h0[i];
        __nv_bfloat16 hi = __float2bfloat16(h);
        __nv_bfloat16 lo = __float2bfloat16(h - __bfloat162float(hi));
        int b = i / HH, k = i % HH;
        g_hsplit[0][(size_t)b * K2 + k] = hi;
        g_hsplit[0][(size_t)b * K2 + HH + k] = lo;
    }
    if (i < TT) g_bar[i] = 0u;
}

__global__ void wsplit_kernel(const float* __restrict__ W) {
    size_t i = (size_t)blockIdx.x * blockDim.x + threadIdx.x;
    if (i < (size_t)G4 * HH) {
        int n = (int)(i / HH), k = (int)(i % HH);
        float w = W[i];
        __nv_bfloat16 hi = __float2bfloat16(w);
        __nv_bfloat16 lo = __float2bfloat16(w - __bfloat162float(hi));
        int r = ((n & 1023) << 2) | (n >> 10);   // gate-interleaved perm
        g_Wsplit[(size_t)r * K2 + k] = hi;
        g_Wsplit[(size_t)r * K2 + HH + k] = lo;
    }
}

// ======================= xproj GEMM (fp32, permuted output) =================
__global__ __launch_bounds__(256) void xproj_kernel(
    const float* __restrict__ inp, const float* __restrict__ W_ih,
    const float* __restrict__ b_ih, const float* __restrict__ b_hh)
{
    __shared__ float As[32][64];
    __shared__ float Bs[32][64];
    const int tid = threadIdx.x;
    const int tx = tid & 15, ty = tid >> 4;
    const int n0 = blockIdx.x * 64, m0 = blockIdx.y * 64;

    float acc[4][4];
#pragma unroll
    for (int r = 0; r < 4; r++)
#pragma unroll
        for (int c = 0; c < 4; c++) acc[r][c] = 0.f;

    for (int k0 = 0; k0 < II; k0 += 32) {
#pragma unroll
        for (int v = 0; v < 2; v++) {
            int e = tid + 256 * v;
            int row = e >> 3, kk = (e & 7) * 4;
            float4 a = *(const float4*)(inp + (size_t)(m0 + row) * II + k0 + kk);
            As[kk + 0][row] = a.x; As[kk + 1][row] = a.y;
            As[kk + 2][row] = a.z; As[kk + 3][row] = a.w;
            float4 b = *(const float4*)(W_ih + (size_t)(n0 + row) * II + k0 + kk);
            Bs[kk + 0][row] = b.x; Bs[kk + 1][row] = b.y;
            Bs[kk + 2][row] = b.z; Bs[kk + 3][row] = b.w;
        }
        __syncthreads();
#pragma unroll
        for (int kk = 0; kk < 32; kk++) {
            float4 av = *(const float4*)(&As[kk][ty * 4]);
            float4 bv = *(const float4*)(&Bs[kk][tx * 4]);
            float a4[4] = {av.x, av.y, av.z, av.w};
            float b4[4] = {bv.x, bv.y, bv.z, bv.w};
#pragma unroll
            for (int r = 0; r < 4; r++)
#pragma unroll
                for (int c = 0; c < 4; c++) acc[r][c] += a4[r] * b4[c];
        }
        __syncthreads();
    }
#pragma unroll
    for (int c = 0; c < 4; c++) {
        int n = n0 + tx * 4 + c;
        float bias = b_ih[n] + b_hh[n];
        int pn = ((n & 1023) << 2) | (n >> 10);
#pragma unroll
        for (int r = 0; r < 4; r++) {
            int m = m0 + ty * 4 + r;
            g_xproj[(size_t)m * G4 + pn] = acc[r][c] + bias;
        }
    }
}

// ======================= persistent LSTM kernel =============================
// grid 128, block 512 (16 warps = 4(M) x 2(N) x 2(KS)). Block owns 32
// permuted gate cols; its W slice stays in smem for all 512 steps. Each
// chunk (32 k) holds two k16-units, processed concurrently by the two
// k-split warp groups; partials reduced through smem at the epilogue.
__global__ __launch_bounds__(NTHR, 1) void lstm_persistent(float* __restrict__ out)
{
    extern __shared__ __align__(16) char smem[];
    const uint32_t sb = smem_to_u32(smem);
    const int tid = threadIdx.x;
    const int wid = tid >> 5, lane = tid & 31;
    const int n0g = blockIdx.x * NBLK;
    const int warp_m = (wid & 3) * 32;
    const int warp_n = ((wid >> 2) & 1) * 16;
    const int ks_id = wid >> 3;              // 0 or 1: which k16-unit of a chunk

    // ---- load W slice (32 rows x 2048 bf16 = 32 x 256 x 16B) into smem ----
    for (int i = tid; i < 8192; i += NTHR) {
        int row = i >> 8, gr = i & 255;
        cp_async16(sb + row * STRW_B + gr * 16,
                   g_Wsplit + (size_t)(n0g + row) * K2 + gr * 8);
    }
    cp_commit();
    asm volatile("cp.async.wait_group 0;" ::: "memory");
    __syncthreads();

    const uint32_t stg0 = sb + W_BYTES;
    const size_t OUT_H = (size_t)TT * BB * HH;
    const int q = lane >> 2, r4 = lane & 3;
    const bool writer = (r4 & 1) == 0;
    const int hl = r4 >> 1;

    for (int t = 0; t < TT; t++) {
        const int rb = t & 1, wb = rb ^ 1;
        const __nv_bfloat16* hbase = g_hsplit[rb];

        auto issueA = [&](int j) {
            if (j < NCH) {
                const int k0 = j * KCH;
                const uint32_t st = stg0 + (j & 3) * STG_B;
#pragma unroll
                for (int i = 0; i < 2; i++) {
                    int idx = tid + (i << 9);       // 0..1023
                    int half = idx >> 9;            // 0: hi, 1: lo
                    int x = idx & 511;
                    int row = x & 127, gr = x >> 7; // 4 x 16B = 32 elems/row
                    cp_async16(st + half * AHI_B + row * STRA_B + gr * 16,
                               hbase + (size_t)row * K2 + half * HH + k0 + gr * 8);
                }
            }
            cp_commit();
        };

        float acc[2][2][4];
#pragma unroll
        for (int mi = 0; mi < 2; mi++)
#pragma unroll
            for (int ni = 0; ni < 2; ni++)
#pragma unroll
                for (int v = 0; v < 4; v++) acc[mi][ni][v] = 0.f;

        issueA(0); issueA(1); issueA(2);

        for (int j = 0; j < NCH; j++) {
            asm volatile("cp.async.wait_group 2;" ::: "memory");
            __syncthreads();
            issueA(j + 3);                    // overwrites stage of chunk j-1
            const uint32_t st = stg0 + (j & 3) * STG_B;
            const int k0 = j * KCH;

            uint32_t ahi[2][4], alo[2][4], bhi[4], blo[4];
            const uint32_t arow = st + (warp_m + (lane & 15)) * STRA_B
                                    + ks_id * 32 + (lane >> 4) * 16;
            ldm_x4(ahi[0], arow);
            ldm_x4(ahi[1], arow + 16 * STRA_B);
            ldm_x4(alo[0], arow + AHI_B);
            ldm_x4(alo[1], arow + AHI_B + 16 * STRA_B);
            const uint32_t brow = sb + (warp_n + (lane & 15)) * STRW_B
                                    + (k0 + ks_id * 16) * 2 + (lane >> 4) * 16;
            ldm_x4(bhi, brow);
            ldm_x4(blo, brow + HH * 2);
#pragma unroll
            for (int mi = 0; mi < 2; mi++)
#pragma unroll
                for (int ni = 0; ni < 2; ni++) {
                    mma_bf16(acc[mi][ni], ahi[mi], bhi[ni], bhi[ni + 2]);
                    mma_bf16(acc[mi][ni], ahi[mi], blo[ni], blo[ni + 2]);
                    mma_bf16(acc[mi][ni], alo[mi], bhi[ni], bhi[ni + 2]);
                }
        }

        // ---------- k-split reduction through drained stage smem ----------
        asm volatile("cp.async.wait_group 0;" ::: "memory");
        __syncthreads();
        {
            float4* red = (float4*)(smem + W_BYTES);
            if (ks_id == 1) {
                float4* p = red + ((wid & 7) * 32 + lane) * 4;
#pragma unroll
                for (int mi = 0; mi < 2; mi++)
#pragma unroll
                    for (int ni = 0; ni < 2; ni++)
                        p[mi * 2 + ni] = *(const float4*)acc[mi][ni];
            }
            __syncthreads();
            if (ks_id == 0) {
                const float4* p = red + ((wid & 7) * 32 + lane) * 4;
#pragma unroll
                for (int mi = 0; mi < 2; mi++)
#pragma unroll
                    for (int ni = 0; ni < 2; ni++) {
                        float4 v = p[mi * 2 + ni];
                        acc[mi][ni][0] += v.x; acc[mi][ni][1] += v.y;
                        acc[mi][ni][2] += v.z; acc[mi][ni][3] += v.w;
                    }
            }
        }

        // ---------- fused LSTM cell epilogue (ks0 warps) ------------------
        if (ks_id == 0) {
            const float* xpb = g_xproj + (size_t)t * BB * G4;
            __nv_bfloat16* hw = g_hsplit[wb];
#pragma unroll
            for (int mi = 0; mi < 2; mi++)
#pragma unroll
                for (int ni = 0; ni < 2; ni++)
#pragma unroll
                    for (int h = 0; h < 2; h++) {
                        float v0 = acc[mi][ni][2 * h];
                        float v1 = acc[mi][ni][2 * h + 1];
                        float p0 = __shfl_xor_sync(0xffffffffu, v0, 1);
                        float p1 = __shfl_xor_sync(0xffffffffu, v1, 1);
                        if (writer) {
                            int m = warp_m + mi * 16 + h * 8 + q;
                            int col = n0g + warp_n + ni * 8 + hl * 4;
                            int hc = col >> 2;
                            float4 xv = *(const float4*)(xpb + (size_t)m * G4 + col);
                            float ig = sigf(v0 + xv.x);
                            float fg = sigf(v1 + xv.y);
                            float gg = tanhf(p0 + xv.z);
                            float og = sigf(p1 + xv.w);
                            size_t cidx = (size_t)m * HH + hc;
                            float cn = fg * g_c[cidx] + ig * gg;
                            g_c[cidx] = cn;
                            float hn = og * tanhf(cn);
                            out[(size_t)t * BB * HH + cidx] = hn;
                            __nv_bfloat16 hi = __float2bfloat16(hn);
                            __nv_bfloat16 lo =
                                __float2bfloat16(hn - __bfloat162float(hi));
                            hw[(size_t)m * K2 + hc] = hi;
                            hw[(size_t)m * K2 + HH + hc] = lo;
                            if (t == TT - 1) {
                                out[OUT_H + cidx] = hn;
                                out[OUT_H + (size_t)BB * HH + cidx] = cn;
                            }
                        }
                    }
        }

        // ---------- grid-wide barrier (all blocks resident) ---------------
        if (t < TT - 1) {
            __syncthreads();
            if (tid == 0) {
                unsigned* bar = &g_bar[t];
                asm volatile("red.release.gpu.global.add.u32 [%0], 1;"
                             :: "l"(bar) : "memory");
                unsigned v;
                do {
                    asm volatile("ld.acquire.gpu.global.u32 %0, [%1];"
                                 : "=r"(v) : "l"(bar));
                } while (v < GRIDN);
            }
            __syncthreads();
        }
    }
}

// ============================================================================
extern "C" void kernel_launch(void* const* d_in, const int* in_sizes, int n_in,
                              void* d_out, int out_size) {
    const float* inputs = (const float*)d_in[0];  // [512,128,256]
    const float* h0     = (const float*)d_in[1];
    const float* c0     = (const float*)d_in[2];
    const float* W_ih   = (const float*)d_in[3];  // [4096,256]
    const float* W_hh   = (const float*)d_in[4];  // [4096,1024]
    const float* b_ih   = (const float*)d_in[5];
    const float* b_hh   = (const float*)d_in[6];
    float* out = (float*)d_out;

    cudaFuncSetAttribute(lstm_persistent,
                         cudaFuncAttributeMaxDynamicSharedMemorySize, SMEM_TOTAL);

    init_state<<<(BB * HH + 255) / 256, 256>>>(h0, c0);
    wsplit_kernel<<<(int)(((size_t)G4 * HH + 255) / 256), 256>>>(W_hh);

    dim3 xgrid(G4 / 64, (TT * BB) / 64);
    xproj_kernel<<<xgrid, 256>>>(inputs, W_ih, b_ih, b_hh);

    lstm_persistent<<<GRIDN, NTHR, SMEM_TOTAL>>>(out);
}

// round 7
// speedup vs baseline: 2.4922x; 1.1408x over previous
#include <cuda_runtime.h>
#include <cuda_bf16.h>
#include <cstdint>
#include <math.h>

#define TT 512
#define BB 128
#define II 256
#define HH 1024
#define G4 (4 * HH)
#define K2 2048               // [hi(1024) | lo(1024)]
#define NBLK 32               // gate-cols per block
#define GRIDN 128             // persistent blocks (<=148 SMs, 1 CTA/SM)
#define NTHR 512              // 16 warps: 4(M) x 2(N) x 2(K-split)
#define KCH 64                // k per pipeline stage
#define NCH (HH / KCH)        // 16 chunks per step
#define STRW_E 2056           // W smem row stride (elems)
#define STRW_B (STRW_E * 2)   // 4112 B
#define STRA_B 144            // A smem row stride (bytes): 64 bf16 + 16B pad
#define W_BYTES (NBLK * STRW_B)          // 131584
#define GRP_HALF (32 * STRA_B)           // 4608 (32 rows, one half)
#define GRP_B (2 * GRP_HALF)             // 9216 per m-group slice
#define STG_B (4 * GRP_B)                // 36864 per stage
#define NSTAGE 2
#define SMEM_TOTAL (W_BYTES + NSTAGE * STG_B)  // 205312

// ---------------- scratch (__device__ globals; allocation-free) -------------
__device__ float g_xproj[(size_t)TT * BB * G4];        // permuted gate cols
__device__ float g_c[BB * HH];
__device__ __nv_bfloat16 g_hsplit[2][BB * K2];         // double-buffered h
__device__ __nv_bfloat16 g_Wsplit[(size_t)G4 * K2];    // [perm row][hi|lo]
__device__ unsigned g_bar[TT];                          // per-step barrier

// ======================= helpers =============================================
__device__ __forceinline__ uint32_t smem_to_u32(const void* p) {
    uint32_t a;
    asm("{ .reg .u64 t; cvta.to.shared.u64 t, %1; cvt.u32.u64 %0, t; }"
        : "=r"(a) : "l"(p));
    return a;
}
__device__ __forceinline__ void cp_async16(uint32_t dst, const void* src) {
    size_t gsrc = __cvta_generic_to_global(src);
    asm volatile("cp.async.cg.shared.global [%0], [%1], 16;"
                 :: "r"(dst), "l"(gsrc) : "memory");
}
__device__ __forceinline__ void cp_commit() {
    asm volatile("cp.async.commit_group;" ::: "memory");
}
__device__ __forceinline__ void bar_named(int id, int cnt) {
    asm volatile("bar.sync %0, %1;" :: "r"(id), "r"(cnt) : "memory");
}
__device__ __forceinline__ void ldm_x4(uint32_t* r, uint32_t addr) {
    asm volatile("ldmatrix.sync.aligned.m8n8.x4.shared.b16 {%0,%1,%2,%3}, [%4];"
                 : "=r"(r[0]), "=r"(r[1]), "=r"(r[2]), "=r"(r[3]) : "r"(addr));
}
__device__ __forceinline__ void mma_bf16(float* d, const uint32_t* a,
                                         uint32_t b0, uint32_t b1) {
    asm volatile(
        "mma.sync.aligned.m16n8k16.row.col.f32.bf16.bf16.f32 "
        "{%0,%1,%2,%3}, {%4,%5,%6,%7}, {%8,%9}, {%0,%1,%2,%3};"
        : "+f"(d[0]), "+f"(d[1]), "+f"(d[2]), "+f"(d[3])
        : "r"(a[0]), "r"(a[1]), "r"(a[2]), "r"(a[3]), "r"(b0), "r"(b1));
}
__device__ __forceinline__ float sigf(float x) { return 1.0f / (1.0f + expf(-x)); }

// ======================= init kernels =======================================
__global__ void init_state(const float* __restrict__ h0, const float* __restrict__ c0) {
    int i = blockIdx.x * blockDim.x + threadIdx.x;
    if (i < BB * HH) {
        g_c[i] = c0[i];
        float h = h0[i];
        __nv_bfloat16 hi = __float2bfloat16(h);
        __nv_bfloat16 lo = __float2bfloat16(h - __bfloat162float(hi));
        int b = i / HH, k = i % HH;
        g_hsplit[0][(size_t)b * K2 + k] = hi;
        g_hsplit[0][(size_t)b * K2 + HH + k] = lo;
    }
    if (i < TT) g_bar[i] = 0u;
}

__global__ void wsplit_kernel(const float* __restrict__ W) {
    size_t i = (size_t)blockIdx.x * blockDim.x + threadIdx.x;
    if (i < (size_t)G4 * HH) {
        int n = (int)(i / HH), k = (int)(i % HH);
        float w = W[i];
        __nv_bfloat16 hi = __float2bfloat16(w);
        __nv_bfloat16 lo = __float2bfloat16(w - __bfloat162float(hi));
        int r = ((n & 1023) << 2) | (n >> 10);   // gate-interleaved perm
        g_Wsplit[(size_t)r * K2 + k] = hi;
        g_Wsplit[(size_t)r * K2 + HH + k] = lo;
    }
}

// ======================= xproj GEMM (fp32, permuted output) =================
__global__ __launch_bounds__(256) void xproj_kernel(
    const float* __restrict__ inp, const float* __restrict__ W_ih,
    const float* __restrict__ b_ih, const float* __restrict__ b_hh)
{
    __shared__ float As[32][64];
    __shared__ float Bs[32][64];
    const int tid = threadIdx.x;
    const int tx = tid & 15, ty = tid >> 4;
    const int n0 = blockIdx.x * 64, m0 = blockIdx.y * 64;

    float acc[4][4];
#pragma unroll
    for (int r = 0; r < 4; r++)
#pragma unroll
        for (int c = 0; c < 4; c++) acc[r][c] = 0.f;

    for (int k0 = 0; k0 < II; k0 += 32) {
#pragma unroll
        for (int v = 0; v < 2; v++) {
            int e = tid + 256 * v;
            int row = e >> 3, kk = (e & 7) * 4;
            float4 a = *(const float4*)(inp + (size_t)(m0 + row) * II + k0 + kk);
            As[kk + 0][row] = a.x; As[kk + 1][row] = a.y;
            As[kk + 2][row] = a.z; As[kk + 3][row] = a.w;
            float4 b = *(const float4*)(W_ih + (size_t)(n0 + row) * II + k0 + kk);
            Bs[kk + 0][row] = b.x; Bs[kk + 1][row] = b.y;
            Bs[kk + 2][row] = b.z; Bs[kk + 3][row] = b.w;
        }
        __syncthreads();
#pragma unroll
        for (int kk = 0; kk < 32; kk++) {
            float4 av = *(const float4*)(&As[kk][ty * 4]);
            float4 bv = *(const float4*)(&Bs[kk][tx * 4]);
            float a4[4] = {av.x, av.y, av.z, av.w};
            float b4[4] = {bv.x, bv.y, bv.z, bv.w};
#pragma unroll
            for (int r = 0; r < 4; r++)
#pragma unroll
                for (int c = 0; c < 4; c++) acc[r][c] += a4[r] * b4[c];
        }
        __syncthreads();
    }
#pragma unroll
    for (int c = 0; c < 4; c++) {
        int n = n0 + tx * 4 + c;
        float bias = b_ih[n] + b_hh[n];
        int pn = ((n & 1023) << 2) | (n >> 10);
#pragma unroll
        for (int r = 0; r < 4; r++) {
            int m = m0 + ty * 4 + r;
            g_xproj[(size_t)m * G4 + pn] = acc[r][c] + bias;
        }
    }
}

// ======================= persistent LSTM kernel =============================
// grid 128, block 512 (16 warps = 4(M) x 2(N) x 2(KS)). W slice (32 gate
// cols) resident in smem. A staged per m-group (disjoint 32-row slices) with
// named-barrier sync, so the 4 m-groups pipeline independently.
__global__ __launch_bounds__(NTHR, 1) void lstm_persistent(float* __restrict__ out)
{
    extern __shared__ __align__(16) char smem[];
    const uint32_t sb = smem_to_u32(smem);
    const int tid = threadIdx.x;
    const int wid = tid >> 5, lane = tid & 31;
    const int n0g = blockIdx.x * NBLK;
    const int mgrp = wid & 3;
    const int warp_m = mgrp * 32;
    const int warp_n = ((wid >> 2) & 1) * 16;
    const int ks_id = wid >> 3;              // 0/1: k16-pair within each chunk
    const int gt = ((wid >> 2) << 5) | lane; // 0..127 within m-group
    const int barid = mgrp + 1;

    // ---- load W slice (32 rows x 2048 bf16 = 32 x 256 x 16B) into smem ----
    for (int i = tid; i < 8192; i += NTHR) {
        int row = i >> 8, gr = i & 255;
        cp_async16(sb + row * STRW_B + gr * 16,
                   g_Wsplit + (size_t)(n0g + row) * K2 + gr * 8);
    }
    cp_commit();
    asm volatile("cp.async.wait_group 0;" ::: "memory");
    __syncthreads();

    const uint32_t stg0 = sb + W_BYTES;
    const size_t OUT_H = (size_t)TT * BB * HH;
    const int q = lane >> 2, r4 = lane & 3;
    const bool writer = (r4 & 1) == 0;
    const int hl = r4 >> 1;

    for (int t = 0; t < TT; t++) {
        const int rb = t & 1, wb = rb ^ 1;
        const __nv_bfloat16* hbase = g_hsplit[rb];

        // copy this m-group's 32-row A slice (hi+lo) for chunk j
        auto issueA = [&](int j) {
            if (j < NCH) {
                const int k0 = j * KCH;
                const uint32_t st = stg0 + (j & 1) * STG_B + mgrp * GRP_B;
#pragma unroll
                for (int u4 = 0; u4 < 4; u4++) {
                    int u = (gt << 2) | u4;        // 0..511
                    int half = u >> 8;             // 0: hi, 1: lo
                    int row = (u >> 3) & 31, c16 = u & 7;
                    cp_async16(st + half * GRP_HALF + row * STRA_B + c16 * 16,
                               hbase + (size_t)(warp_m + row) * K2
                                     + half * HH + k0 + c16 * 8);
                }
            }
            cp_commit();
        };

        float acc[2][2][4];
#pragma unroll
        for (int mi = 0; mi < 2; mi++)
#pragma unroll
            for (int ni = 0; ni < 2; ni++)
#pragma unroll
                for (int v = 0; v < 4; v++) acc[mi][ni][v] = 0.f;

        issueA(0); issueA(1);

        for (int j = 0; j < NCH; j++) {
            asm volatile("cp.async.wait_group 1;" ::: "memory");
            bar_named(barid, 128);               // slice j visible to group

            const uint32_t st = stg0 + (j & 1) * STG_B + mgrp * GRP_B;
            uint32_t ahi[2][2][4], alo[2][2][4], bhi[2][4], blo[2][4];
#pragma unroll
            for (int mi = 0; mi < 2; mi++) {
                const uint32_t abase = st + (mi * 16 + (lane & 15)) * STRA_B
                                          + (lane >> 4) * 16 + ks_id * 64;
#pragma unroll
                for (int u = 0; u < 2; u++) {
                    ldm_x4(ahi[mi][u], abase + u * 32);
                    ldm_x4(alo[mi][u], abase + u * 32 + GRP_HALF);
                }
            }
#pragma unroll
            for (int u = 0; u < 2; u++) {
                const int kk = j * KCH + ks_id * 32 + u * 16;
                const uint32_t baddr = sb + (warp_n + (lane & 15)) * STRW_B
                                          + kk * 2 + (lane >> 4) * 16;
                ldm_x4(bhi[u], baddr);
                ldm_x4(blo[u], baddr + HH * 2);
            }
            bar_named(barid, 128);               // group reads done
            issueA(j + 2);                       // safe to overwrite stage

#pragma unroll
            for (int u = 0; u < 2; u++)
#pragma unroll
                for (int mi = 0; mi < 2; mi++)
#pragma unroll
                    for (int ni = 0; ni < 2; ni++) {
                        mma_bf16(acc[mi][ni], ahi[mi][u], bhi[u][ni], bhi[u][ni + 2]);
                        mma_bf16(acc[mi][ni], ahi[mi][u], blo[u][ni], blo[u][ni + 2]);
                        mma_bf16(acc[mi][ni], alo[mi][u], bhi[u][ni], bhi[u][ni + 2]);
                    }
        }

        // ---------- k-split reduction through smem (stage region idle) -----
        asm volatile("cp.async.wait_group 0;" ::: "memory");
        __syncthreads();
        {
            float4* red = (float4*)(smem + W_BYTES);
            if (ks_id == 1) {
                float4* p = red + ((wid & 7) * 32 + lane) * 4;
#pragma unroll
                for (int mi = 0; mi < 2; mi++)
#pragma unroll
                    for (int ni = 0; ni < 2; ni++)
                        p[mi * 2 + ni] = *(const float4*)acc[mi][ni];
            }
            __syncthreads();
            if (ks_id == 0) {
                const float4* p = red + ((wid & 7) * 32 + lane) * 4;
#pragma unroll
                for (int mi = 0; mi < 2; mi++)
#pragma unroll
                    for (int ni = 0; ni < 2; ni++) {
                        float4 v = p[mi * 2 + ni];
                        acc[mi][ni][0] += v.x; acc[mi][ni][1] += v.y;
                        acc[mi][ni][2] += v.z; acc[mi][ni][3] += v.w;
                    }
            }
        }

        // ---------- fused LSTM cell epilogue (ks0 warps) ------------------
        if (ks_id == 0) {
            const float* xpb = g_xproj + (size_t)t * BB * G4;
            __nv_bfloat16* hw = g_hsplit[wb];
#pragma unroll
            for (int mi = 0; mi < 2; mi++)
#pragma unroll
                for (int ni = 0; ni < 2; ni++)
#pragma unroll
                    for (int h = 0; h < 2; h++) {
                        float v0 = acc[mi][ni][2 * h];
                        float v1 = acc[mi][ni][2 * h + 1];
                        float p0 = __shfl_xor_sync(0xffffffffu, v0, 1);
                        float p1 = __shfl_xor_sync(0xffffffffu, v1, 1);
                        if (writer) {
                            int m = warp_m + mi * 16 + h * 8 + q;
                            int col = n0g + warp_n + ni * 8 + hl * 4;
                            int hc = col >> 2;
                            float4 xv = *(const float4*)(xpb + (size_t)m * G4 + col);
                            float ig = sigf(v0 + xv.x);
                            float fg = sigf(v1 + xv.y);
                            float gg = tanhf(p0 + xv.z);
                            float og = sigf(p1 + xv.w);
                            size_t cidx = (size_t)m * HH + hc;
                            float cn = fg * g_c[cidx] + ig * gg;
                            g_c[cidx] = cn;
                            float hn = og * tanhf(cn);
                            out[(size_t)t * BB * HH + cidx] = hn;
                            __nv_bfloat16 hi = __float2bfloat16(hn);
                            __nv_bfloat16 lo =
                                __float2bfloat16(hn - __bfloat162float(hi));
                            hw[(size_t)m * K2 + hc] = hi;
                            hw[(size_t)m * K2 + HH + hc] = lo;
                            if (t == TT - 1) {
                                out[OUT_H + cidx] = hn;
                                out[OUT_H + (size_t)BB * HH + cidx] = cn;
                            }
                        }
                    }
        }

        // ---------- grid-wide barrier (all blocks resident) ---------------
        if (t < TT - 1) {
            __syncthreads();
            if (tid == 0) {
                unsigned* bar = &g_bar[t];
                asm volatile("red.release.gpu.global.add.u32 [%0], 1;"
                             :: "l"(bar) : "memory");
                unsigned v;
                do {
                    asm volatile("ld.acquire.gpu.global.u32 %0, [%1];"
                                 : "=r"(v) : "l"(bar));
                } while (v < GRIDN);
            }
            __syncthreads();
        }
    }
}

// ============================================================================
extern "C" void kernel_launch(void* const* d_in, const int* in_sizes, int n_in,
                              void* d_out, int out_size) {
    const float* inputs = (const float*)d_in[0];  // [512,128,256]
    const float* h0     = (const float*)d_in[1];
    const float* c0     = (const float*)d_in[2];
    const float* W_ih   = (const float*)d_in[3];  // [4096,256]
    const float* W_hh   = (const float*)d_in[4];  // [4096,1024]
    const float* b_ih   = (const float*)d_in[5];
    const float* b_hh   = (const float*)d_in[6];
    float* out = (float*)d_out;

    cudaFuncSetAttribute(lstm_persistent,
                         cudaFuncAttributeMaxDynamicSharedMemorySize, SMEM_TOTAL);

    init_state<<<(BB * HH + 255) / 256, 256>>>(h0, c0);
    wsplit_kernel<<<(int)(((size_t)G4 * HH + 255) / 256), 256>>>(W_hh);

    dim3 xgrid(G4 / 64, (TT * BB) / 64);
    xproj_kernel<<<xgrid, 256>>>(inputs, W_ih, b_ih, b_hh);

    lstm_persistent<<<GRIDN, NTHR, SMEM_TOTAL>>>(out);
}

// round 8
// speedup vs baseline: 2.6055x; 1.0455x over previous
#include <cuda_runtime.h>
#include <cuda_fp16.h>
#include <cstdint>
#include <math.h>

#define TT 512
#define BB 128
#define II 256
#define HH 1024
#define G4 (4 * HH)
#define K2 2048               // W: [hi(1024) | lo(1024)] fp16
#define NBLK 32               // gate-cols per block
#define GRIDN 128             // persistent blocks (<=148 SMs, 1 CTA/SM)
#define NTHR 512              // 16 warps: 4(M) x 4(KS)
#define KCH 64                // k per pipeline stage
#define NCH (HH / KCH)        // 16 chunks per step
#define STRW_B 4112           // W smem row stride: 2048 fp16 + 16B pad
#define STRA_B 144            // A smem row stride: 64 fp16 (128B) + 16B pad
#define W_BYTES (NBLK * STRW_B)          // 131584
#define GRP_B (32 * STRA_B)              // 4608 per m-group slice
#define STG_B (4 * GRP_B)                // 18432 per stage
#define NSTAGE 4
#define SMEM_TOTAL (W_BYTES + NSTAGE * STG_B)  // 205312

// ---------------- scratch (__device__ globals; allocation-free) -------------
__device__ float g_xproj[(size_t)TT * BB * G4];        // permuted gate cols
__device__ float g_c[BB * HH];
__device__ __half g_h[2][BB * HH];                     // double-buffered h fp16
__device__ __half g_Wsplit[(size_t)G4 * K2];           // [perm row][hi|lo]
__device__ unsigned g_bar[TT];                          // per-step barrier

// ======================= helpers =============================================
__device__ __forceinline__ uint32_t smem_to_u32(const void* p) {
    uint32_t a;
    asm("{ .reg .u64 t; cvta.to.shared.u64 t, %1; cvt.u32.u64 %0, t; }"
        : "=r"(a) : "l"(p));
    return a;
}
__device__ __forceinline__ void cp_async16(uint32_t dst, const void* src) {
    size_t gsrc = __cvta_generic_to_global(src);
    asm volatile("cp.async.cg.shared.global [%0], [%1], 16;"
                 :: "r"(dst), "l"(gsrc) : "memory");
}
__device__ __forceinline__ void cp_commit() {
    asm volatile("cp.async.commit_group;" ::: "memory");
}
__device__ __forceinline__ void bar_named(int id, int cnt) {
    asm volatile("bar.sync %0, %1;" :: "r"(id), "r"(cnt) : "memory");
}
__device__ __forceinline__ void ldm_x4(uint32_t* r, uint32_t addr) {
    asm volatile("ldmatrix.sync.aligned.m8n8.x4.shared.b16 {%0,%1,%2,%3}, [%4];"
                 : "=r"(r[0]), "=r"(r[1]), "=r"(r[2]), "=r"(r[3]) : "r"(addr));
}
__device__ __forceinline__ void mma_fp16(float* d, const uint32_t* a,
                                         uint32_t b0, uint32_t b1) {
    asm volatile(
        "mma.sync.aligned.m16n8k16.row.col.f32.f16.f16.f32 "
        "{%0,%1,%2,%3}, {%4,%5,%6,%7}, {%8,%9}, {%0,%1,%2,%3};"
        : "+f"(d[0]), "+f"(d[1]), "+f"(d[2]), "+f"(d[3])
        : "r"(a[0]), "r"(a[1]), "r"(a[2]), "r"(a[3]), "r"(b0), "r"(b1));
}
__device__ __forceinline__ float sigf(float x) { return 1.0f / (1.0f + expf(-x)); }

// ======================= init kernels =======================================
__global__ void init_state(const float* __restrict__ h0, const float* __restrict__ c0) {
    int i = blockIdx.x * blockDim.x + threadIdx.x;
    if (i < BB * HH) {
        g_c[i] = c0[i];
        g_h[0][i] = __float2half(h0[i]);
    }
    if (i < TT) g_bar[i] = 0u;
}

__global__ void wsplit_kernel(const float* __restrict__ W) {
    size_t i = (size_t)blockIdx.x * blockDim.x + threadIdx.x;
    if (i < (size_t)G4 * HH) {
        int n = (int)(i / HH), k = (int)(i % HH);
        float w = W[i];
        __half hi = __float2half(w);
        __half lo = __float2half(w - __half2float(hi));
        int r = ((n & 1023) << 2) | (n >> 10);   // gate-interleaved perm
        g_Wsplit[(size_t)r * K2 + k] = hi;
        g_Wsplit[(size_t)r * K2 + HH + k] = lo;
    }
}

// ======================= xproj GEMM (fp32, permuted output) =================
__global__ __launch_bounds__(256) void xproj_kernel(
    const float* __restrict__ inp, const float* __restrict__ W_ih,
    const float* __restrict__ b_ih, const float* __restrict__ b_hh)
{
    __shared__ float As[32][64];
    __shared__ float Bs[32][64];
    const int tid = threadIdx.x;
    const int tx = tid & 15, ty = tid >> 4;
    const int n0 = blockIdx.x * 64, m0 = blockIdx.y * 64;

    float acc[4][4];
#pragma unroll
    for (int r = 0; r < 4; r++)
#pragma unroll
        for (int c = 0; c < 4; c++) acc[r][c] = 0.f;

    for (int k0 = 0; k0 < II; k0 += 32) {
#pragma unroll
        for (int v = 0; v < 2; v++) {
            int e = tid + 256 * v;
            int row = e >> 3, kk = (e & 7) * 4;
            float4 a = *(const float4*)(inp + (size_t)(m0 + row) * II + k0 + kk);
            As[kk + 0][row] = a.x; As[kk + 1][row] = a.y;
            As[kk + 2][row] = a.z; As[kk + 3][row] = a.w;
            float4 b = *(const float4*)(W_ih + (size_t)(n0 + row) * II + k0 + kk);
            Bs[kk + 0][row] = b.x; Bs[kk + 1][row] = b.y;
            Bs[kk + 2][row] = b.z; Bs[kk + 3][row] = b.w;
        }
        __syncthreads();
#pragma unroll
        for (int kk = 0; kk < 32; kk++) {
            float4 av = *(const float4*)(&As[kk][ty * 4]);
            float4 bv = *(const float4*)(&Bs[kk][tx * 4]);
            float a4[4] = {av.x, av.y, av.z, av.w};
            float b4[4] = {bv.x, bv.y, bv.z, bv.w};
#pragma unroll
            for (int r = 0; r < 4; r++)
#pragma unroll
                for (int c = 0; c < 4; c++) acc[r][c] += a4[r] * b4[c];
        }
        __syncthreads();
    }
#pragma unroll
    for (int c = 0; c < 4; c++) {
        int n = n0 + tx * 4 + c;
        float bias = b_ih[n] + b_hh[n];
        int pn = ((n & 1023) << 2) | (n >> 10);
#pragma unroll
        for (int r = 0; r < 4; r++) {
            int m = m0 + ty * 4 + r;
            g_xproj[(size_t)m * G4 + pn] = acc[r][c] + bias;
        }
    }
}

// ======================= persistent LSTM kernel =============================
// grid 128, block 512 (16 warps = 4(M) x 4(KS)). W slice (32 gate cols,
// hi+lo fp16) resident in smem. A (fp16, single copy) staged per m-group.
// Warp tile: M32 x N32 x k16; 2 MMA terms (A*Whi + A*Wlo); KS partials
// reduced through smem, fused LSTM cell epilogue on ks0 warps.
__global__ __launch_bounds__(NTHR, 1) void lstm_persistent(float* __restrict__ out)
{
    extern __shared__ __align__(16) char smem[];
    const uint32_t sb = smem_to_u32(smem);
    const int tid = threadIdx.x;
    const int wid = tid >> 5, lane = tid & 31;
    const int n0g = blockIdx.x * NBLK;
    const int mgrp = wid & 3;
    const int warp_m = mgrp * 32;
    const int ks_id = wid >> 2;              // 0..3: k16-unit within chunk
    const int gt = (ks_id << 5) | lane;      // 0..127 within m-group
    const int barid = mgrp + 1;

    // ---- load W slice (32 rows x 2048 fp16 = 32 x 256 x 16B) into smem ----
    for (int i = tid; i < 8192; i += NTHR) {
        int row = i >> 8, gr = i & 255;
        cp_async16(sb + row * STRW_B + gr * 16,
                   g_Wsplit + (size_t)(n0g + row) * K2 + gr * 8);
    }
    cp_commit();
    asm volatile("cp.async.wait_group 0;" ::: "memory");
    __syncthreads();

    const uint32_t stg0 = sb + W_BYTES;
    const size_t OUT_H = (size_t)TT * BB * HH;
    const int q = lane >> 2, r4 = lane & 3;
    const bool writer = (r4 & 1) == 0;
    const int hl = r4 >> 1;

    for (int t = 0; t < TT; t++) {
        const int rb = t & 1, wb = rb ^ 1;
        const __half* hbase = g_h[rb];

        // copy this m-group's 32-row A slice (fp16 hi only) for chunk j
        auto issueA = [&](int j) {
            if (j < NCH) {
                const int k0 = j * KCH;
                const uint32_t st = stg0 + (j & 3) * STG_B + mgrp * GRP_B;
#pragma unroll
                for (int i = 0; i < 2; i++) {
                    int u = (gt << 1) | i;          // 0..255
                    int row = u >> 3, c16 = u & 7;  // 32 rows x 8 groups
                    cp_async16(st + row * STRA_B + c16 * 16,
                               hbase + (size_t)(warp_m + row) * HH + k0 + c16 * 8);
                }
            }
            cp_commit();
        };

        float acc[2][4][4];
#pragma unroll
        for (int mi = 0; mi < 2; mi++)
#pragma unroll
            for (int nf = 0; nf < 4; nf++)
#pragma unroll
                for (int v = 0; v < 4; v++) acc[mi][nf][v] = 0.f;

        issueA(0); issueA(1); issueA(2);

        for (int j = 0; j < NCH; j++) {
            asm volatile("cp.async.wait_group 2;" ::: "memory");
            bar_named(barid, 128);               // slice j visible to group

            const uint32_t st = stg0 + (j & 3) * STG_B + mgrp * GRP_B;
            uint32_t a[2][4], bhi[2][4], blo[2][4];
            const uint32_t abase = st + (lane & 15) * STRA_B
                                      + (lane >> 4) * 16 + ks_id * 32;
            ldm_x4(a[0], abase);
            ldm_x4(a[1], abase + 16 * STRA_B);
            const int kk = j * KCH + ks_id * 16;
#pragma unroll
            for (int nh = 0; nh < 2; nh++) {
                const uint32_t baddr = sb + (nh * 16 + (lane & 15)) * STRW_B
                                          + kk * 2 + (lane >> 4) * 16;
                ldm_x4(bhi[nh], baddr);
                ldm_x4(blo[nh], baddr + HH * 2);
            }
            bar_named(barid, 128);               // group reads done
            issueA(j + 3);                       // overwrite stage of j-1

#pragma unroll
            for (int mi = 0; mi < 2; mi++)
#pragma unroll
                for (int nh = 0; nh < 2; nh++)
#pragma unroll
                    for (int sub = 0; sub < 2; sub++) {
                        mma_fp16(acc[mi][nh * 2 + sub], a[mi],
                                 bhi[nh][sub], bhi[nh][sub + 2]);
                        mma_fp16(acc[mi][nh * 2 + sub], a[mi],
                                 blo[nh][sub], blo[nh][sub + 2]);
                    }
        }

        // ---------- KS reduction through stage smem (f-major layout) -------
        asm volatile("cp.async.wait_group 0;" ::: "memory");
        __syncthreads();
        {
            float4* red = (float4*)(smem + W_BYTES);
            const int slot = mgrp * 32 + lane;       // 0..127
            if (ks_id > 0) {
                float4* p = red + (ks_id - 1) * 128 + slot;
#pragma unroll
                for (int mi = 0; mi < 2; mi++)
#pragma unroll
                    for (int nf = 0; nf < 4; nf++)
                        p[(mi * 4 + nf) * 384] = *(const float4*)acc[mi][nf];
            }
            __syncthreads();
            if (ks_id == 0) {
#pragma unroll
                for (int mi = 0; mi < 2; mi++)
#pragma unroll
                    for (int nf = 0; nf < 4; nf++) {
                        const float4* p = red + (mi * 4 + nf) * 384 + slot;
#pragma unroll
                        for (int s = 0; s < 3; s++) {
                            float4 v = p[s * 128];
                            acc[mi][nf][0] += v.x; acc[mi][nf][1] += v.y;
                            acc[mi][nf][2] += v.z; acc[mi][nf][3] += v.w;
                        }
                    }
            }
        }

        // ---------- fused LSTM cell epilogue (ks0 warps) ------------------
        if (ks_id == 0) {
            const float* xpb = g_xproj + (size_t)t * BB * G4;
            __half* hw = g_h[wb];
#pragma unroll
            for (int mi = 0; mi < 2; mi++)
#pragma unroll
                for (int nf = 0; nf < 4; nf++)
#pragma unroll
                    for (int h = 0; h < 2; h++) {
                        float v0 = acc[mi][nf][2 * h];
                        float v1 = acc[mi][nf][2 * h + 1];
                        float p0 = __shfl_xor_sync(0xffffffffu, v0, 1);
                        float p1 = __shfl_xor_sync(0xffffffffu, v1, 1);
                        if (writer) {
                            int m = warp_m + mi * 16 + h * 8 + q;
                            int col = n0g + nf * 8 + hl * 4;
                            int hc = col >> 2;
                            float4 xv = *(const float4*)(xpb + (size_t)m * G4 + col);
                            float ig = sigf(v0 + xv.x);
                            float fg = sigf(v1 + xv.y);
                            float gg = tanhf(p0 + xv.z);
                            float og = sigf(p1 + xv.w);
                            size_t cidx = (size_t)m * HH + hc;
                            float cn = fg * g_c[cidx] + ig * gg;
                            g_c[cidx] = cn;
                            float hn = og * tanhf(cn);
                            out[(size_t)t * BB * HH + cidx] = hn;
                            hw[cidx] = __float2half(hn);
                            if (t == TT - 1) {
                                out[OUT_H + cidx] = hn;
                                out[OUT_H + (size_t)BB * HH + cidx] = cn;
                            }
                        }
                    }
        }

        // ---------- grid-wide barrier (all blocks resident) ---------------
        if (t < TT - 1) {
            __syncthreads();
            if (tid == 0) {
                unsigned* bar = &g_bar[t];
                asm volatile("red.release.gpu.global.add.u32 [%0], 1;"
                             :: "l"(bar) : "memory");
                unsigned v;
                do {
                    asm volatile("ld.acquire.gpu.global.u32 %0, [%1];"
                                 : "=r"(v) : "l"(bar));
                } while (v < GRIDN);
            }
            __syncthreads();
        }
    }
}

// ============================================================================
extern "C" void kernel_launch(void* const* d_in, const int* in_sizes, int n_in,
                              void* d_out, int out_size) {
    const float* inputs = (const float*)d_in[0];  // [512,128,256]
    const float* h0     = (const float*)d_in[1];
    const float* c0     = (const float*)d_in[2];
    const float* W_ih   = (const float*)d_in[3];  // [4096,256]
    const float* W_hh   = (const float*)d_in[4];  // [4096,1024]
    const float* b_ih   = (const float*)d_in[5];
    const float* b_hh   = (const float*)d_in[6];
    float* out = (float*)d_out;

    cudaFuncSetAttribute(lstm_persistent,
                         cudaFuncAttributeMaxDynamicSharedMemorySize, SMEM_TOTAL);

    init_state<<<(BB * HH + 255) / 256, 256>>>(h0, c0);
    wsplit_kernel<<<(int)(((size_t)G4 * HH + 255) / 256), 256>>>(W_hh);

    dim3 xgrid(G4 / 64, (TT * BB) / 64);
    xproj_kernel<<<xgrid, 256>>>(inputs, W_ih, b_ih, b_hh);

    lstm_persistent<<<GRIDN, NTHR, SMEM_TOTAL>>>(out);
}

// round 9
// speedup vs baseline: 2.6496x; 1.0169x over previous
#include <cuda_runtime.h>
#include <cuda_fp16.h>
#include <cstdint>
#include <math.h>

#define TT 512
#define BB 128
#define II 256
#define HH 1024
#define G4 (4 * HH)
#define K2 2048               // W: [hi(1024) | lo(1024)] fp16
#define NBLK 32               // gate-cols per block (8 hcols)
#define GRIDN 128
#define NTHR 512              // 16 warps: 4(M) x 4(KS)
#define KCH 64
#define NCH (HH / KCH)        // 16
#define STRW_B 4112
#define STRA_B 144
#define W_BYTES (NBLK * STRW_B)          // 131584
#define GRP_B (32 * STRA_B)              // 4608
#define STG_B (4 * GRP_B)                // 18432
#define XP_OFF (W_BYTES + 4 * STG_B)     // 205312
#define C_OFF (XP_OFF + 4 * 4608)        // 223744
#define SMEM_TOTAL (C_OFF + 4096)        // 227840

// ---------------- scratch ---------------------------------------------------
__device__ float g_xproj[(size_t)TT * BB * G4];
__device__ __half g_h[2][BB * HH];
__device__ __half g_Wsplit[(size_t)G4 * K2];
__device__ unsigned g_flag[TT * 64];     // [t][chunk 0..15][mgrp 0..3] -> 8
__device__ unsigned g_ack[TT];           // mainloop-done acks -> 512

// ======================= helpers =============================================
__device__ __forceinline__ uint32_t smem_to_u32(const void* p) {
    uint32_t a;
    asm("{ .reg .u64 t; cvta.to.shared.u64 t, %1; cvt.u32.u64 %0, t; }"
        : "=r"(a) : "l"(p));
    return a;
}
__device__ __forceinline__ void cp_async16(uint32_t dst, const void* src) {
    size_t gsrc = __cvta_generic_to_global(src);
    asm volatile("cp.async.cg.shared.global [%0], [%1], 16;"
                 :: "r"(dst), "l"(gsrc) : "memory");
}
__device__ __forceinline__ void cp_commit() {
    asm volatile("cp.async.commit_group;" ::: "memory");
}
__device__ __forceinline__ void bar_named(int id, int cnt) {
    asm volatile("bar.sync %0, %1;" :: "r"(id), "r"(cnt) : "memory");
}
__device__ __forceinline__ void ldm_x4(uint32_t* r, uint32_t addr) {
    asm volatile("ldmatrix.sync.aligned.m8n8.x4.shared.b16 {%0,%1,%2,%3}, [%4];"
                 : "=r"(r[0]), "=r"(r[1]), "=r"(r[2]), "=r"(r[3]) : "r"(addr));
}
__device__ __forceinline__ void mma_fp16(float* d, const uint32_t* a,
                                         uint32_t b0, uint32_t b1) {
    asm volatile(
        "mma.sync.aligned.m16n8k16.row.col.f32.f16.f16.f32 "
        "{%0,%1,%2,%3}, {%4,%5,%6,%7}, {%8,%9}, {%0,%1,%2,%3};"
        : "+f"(d[0]), "+f"(d[1]), "+f"(d[2]), "+f"(d[3])
        : "r"(a[0]), "r"(a[1]), "r"(a[2]), "r"(a[3]), "r"(b0), "r"(b1));
}
__device__ __forceinline__ unsigned ld_acq(const unsigned* p) {
    unsigned v;
    asm volatile("ld.acquire.gpu.global.u32 %0, [%1];" : "=r"(v) : "l"(p));
    return v;
}
__device__ __forceinline__ void red_relax(unsigned* p) {
    asm volatile("red.relaxed.gpu.global.add.u32 [%0], 1;" :: "l"(p) : "memory");
}
__device__ __forceinline__ void red_rel(unsigned* p) {
    asm volatile("red.release.gpu.global.add.u32 [%0], 1;" :: "l"(p) : "memory");
}
__device__ __forceinline__ float sigf(float x) { return 1.0f / (1.0f + expf(-x)); }

// ======================= init kernels =======================================
__global__ void init_state(const float* __restrict__ h0) {
    int i = blockIdx.x * blockDim.x + threadIdx.x;
    if (i < BB * HH) g_h[0][i] = __float2half(h0[i]);
    if (i < TT * 64) g_flag[i] = 0u;
    if (i < TT) g_ack[i] = 0u;
}

__global__ void wsplit_kernel(const float* __restrict__ W) {
    size_t i = (size_t)blockIdx.x * blockDim.x + threadIdx.x;
    if (i < (size_t)G4 * HH) {
        int n = (int)(i / HH), k = (int)(i % HH);
        float w = W[i];
        __half hi = __float2half(w);
        __half lo = __float2half(w - __half2float(hi));
        int r = ((n & 1023) << 2) | (n >> 10);
        g_Wsplit[(size_t)r * K2 + k] = hi;
        g_Wsplit[(size_t)r * K2 + HH + k] = lo;
    }
}

// ======================= xproj GEMM (fp32, permuted output) =================
__global__ __launch_bounds__(256) void xproj_kernel(
    const float* __restrict__ inp, const float* __restrict__ W_ih,
    const float* __restrict__ b_ih, const float* __restrict__ b_hh)
{
    __shared__ float As[32][64];
    __shared__ float Bs[32][64];
    const int tid = threadIdx.x;
    const int tx = tid & 15, ty = tid >> 4;
    const int n0 = blockIdx.x * 64, m0 = blockIdx.y * 64;

    float acc[4][4];
#pragma unroll
    for (int r = 0; r < 4; r++)
#pragma unroll
        for (int c = 0; c < 4; c++) acc[r][c] = 0.f;

    for (int k0 = 0; k0 < II; k0 += 32) {
#pragma unroll
        for (int v = 0; v < 2; v++) {
            int e = tid + 256 * v;
            int row = e >> 3, kk = (e & 7) * 4;
            float4 a = *(const float4*)(inp + (size_t)(m0 + row) * II + k0 + kk);
            As[kk + 0][row] = a.x; As[kk + 1][row] = a.y;
            As[kk + 2][row] = a.z; As[kk + 3][row] = a.w;
            float4 b = *(const float4*)(W_ih + (size_t)(n0 + row) * II + k0 + kk);
            Bs[kk + 0][row] = b.x; Bs[kk + 1][row] = b.y;
            Bs[kk + 2][row] = b.z; Bs[kk + 3][row] = b.w;
        }
        __syncthreads();
#pragma unroll
        for (int kk = 0; kk < 32; kk++) {
            float4 av = *(const float4*)(&As[kk][ty * 4]);
            float4 bv = *(const float4*)(&Bs[kk][tx * 4]);
            float a4[4] = {av.x, av.y, av.z, av.w};
            float b4[4] = {bv.x, bv.y, bv.z, bv.w};
#pragma unroll
            for (int r = 0; r < 4; r++)
#pragma unroll
                for (int c = 0; c < 4; c++) acc[r][c] += a4[r] * b4[c];
        }
        __syncthreads();
    }
#pragma unroll
    for (int c = 0; c < 4; c++) {
        int n = n0 + tx * 4 + c;
        float bias = b_ih[n] + b_hh[n];
        int pn = ((n & 1023) << 2) | (n >> 10);
#pragma unroll
        for (int r = 0; r < 4; r++) {
            int m = m0 + ty * 4 + r;
            g_xproj[(size_t)m * G4 + pn] = acc[r][c] + bias;
        }
    }
}

// ======================= persistent LSTM, dataflow-synced ===================
__global__ __launch_bounds__(NTHR, 1) void lstm_persistent(
    float* __restrict__ out, const float* __restrict__ c0)
{
    extern __shared__ __align__(16) char smem[];
    const uint32_t sb = smem_to_u32(smem);
    const int tid = threadIdx.x;
    const int wid = tid >> 5, lane = tid & 31;
    const int bidx = blockIdx.x;
    const int n0g = bidx * NBLK;
    const int mgrp = wid & 3;
    const int warp_m = mgrp * 32;
    const int ks = wid >> 2;                 // 0..3
    const int barid = mgrp + 1;
    const int boff = bidx & 15;

    // ---- W slice into smem (once) ----
    for (int i = tid; i < 8192; i += NTHR) {
        int row = i >> 8, gr = i & 255;
        cp_async16(sb + row * STRW_B + gr * 16,
                   g_Wsplit + (size_t)(n0g + row) * K2 + gr * 8);
    }
    cp_commit();
    asm volatile("cp.async.wait_group 0;" ::: "memory");
    // ---- c slice into smem (once) ----
    float* c_s = (float*)(smem + C_OFF);
    for (int i = tid; i < 1024; i += NTHR) {
        int row = i >> 3, hcl = i & 7;
        c_s[i] = c0[(size_t)row * HH + bidx * 8 + hcl];
    }
    __syncthreads();

    const uint32_t stg0 = sb + W_BYTES;
    const size_t OUT_H = (size_t)TT * BB * HH;
    const int q = lane >> 2, r4 = lane & 3;
    const bool writer = (r4 & 1) == 0;
    const int hl = r4 >> 1;
    const int gtid = ks * 32 + lane;         // 0..127 within m-group

    for (int t = 0; t < TT; t++) {
        const int rb = t & 1, wb = rb ^ 1;
        const __half* hbase = g_h[rb];
        const unsigned* fl = g_flag + (size_t)(t - 1) * 64;

        // xproj prefetch for THIS step (ks0 warp owns the buffer)
        if (ks == 0) {
            const float* xs = g_xproj + ((size_t)t * BB + warp_m) * G4 + n0g;
            const uint32_t xd = sb + XP_OFF + mgrp * 4608;
            for (int i = lane; i < 256; i += 32) {
                int row = i >> 3, c16 = i & 7;
                cp_async16(xd + row * 144 + c16 * 16,
                           xs + (size_t)row * G4 + c16 * 4);
            }
        }

        auto issueA = [&](int j, unsigned fv) {
            if (j < NCH) {
                const int jp = (j + boff) & 15;
                if (t > 0) {
                    const unsigned* fp = fl + jp * 4 + mgrp;
                    unsigned v = fv;
                    while (v < 8u) { __nanosleep(64); v = ld_acq(fp); }
                }
                const int k0 = jp * KCH;
                const uint32_t st = stg0 + (j & 3) * STG_B + mgrp * GRP_B;
#pragma unroll
                for (int i2 = 0; i2 < 2; i2++) {
                    int u = gtid * 2 + i2;
                    int row = u >> 3, c16 = u & 7;
                    cp_async16(st + row * STRA_B + c16 * 16,
                               hbase + (size_t)(warp_m + row) * HH + k0 + c16 * 8);
                }
            }
            cp_commit();
        };
        auto probe = [&](int j) -> unsigned {
            if (t == 0 || j >= NCH) return 8u;
            return __ldcg(fl + ((j + boff) & 15) * 4 + mgrp);
        };

        float acc[2][4][4];
#pragma unroll
        for (int mi = 0; mi < 2; mi++)
#pragma unroll
            for (int nf = 0; nf < 4; nf++)
#pragma unroll
                for (int v = 0; v < 4; v++) acc[mi][nf][v] = 0.f;

        issueA(0, probe(0)); issueA(1, probe(1)); issueA(2, probe(2));
        unsigned fnext = probe(3);

        for (int j = 0; j < NCH; j++) {
            asm volatile("cp.async.wait_group 2;" ::: "memory");
            bar_named(barid, 128);

            const int jp = (j + boff) & 15;
            const uint32_t st = stg0 + (j & 3) * STG_B + mgrp * GRP_B;
            uint32_t a[2][4], bhi[2][4], blo[2][4];
            const uint32_t abase = st + (lane & 15) * STRA_B
                                      + (lane >> 4) * 16 + ks * 32;
            ldm_x4(a[0], abase);
            ldm_x4(a[1], abase + 16 * STRA_B);
            const int kk = jp * KCH + ks * 16;
#pragma unroll
            for (int nh = 0; nh < 2; nh++) {
                const uint32_t baddr = sb + (nh * 16 + (lane & 15)) * STRW_B
                                          + kk * 2 + (lane >> 4) * 16;
                ldm_x4(bhi[nh], baddr);
                ldm_x4(blo[nh], baddr + HH * 2);
            }
            unsigned fcur = fnext;
            fnext = probe(j + 4);
            issueA(j + 3, fcur);

#pragma unroll
            for (int mi = 0; mi < 2; mi++)
#pragma unroll
                for (int nh = 0; nh < 2; nh++)
#pragma unroll
                    for (int sub = 0; sub < 2; sub++) {
                        mma_fp16(acc[mi][nh * 2 + sub], a[mi],
                                 bhi[nh][sub], bhi[nh][sub + 2]);
                        mma_fp16(acc[mi][nh * 2 + sub], a[mi],
                                 blo[nh][sub], blo[nh][sub + 2]);
                    }
        }

        asm volatile("cp.async.wait_group 0;" ::: "memory");
        bar_named(barid, 128);
        if (ks == 3 && lane == 0) red_relax(&g_ack[t]);   // group reads done

        // ---------- KS partials via this group's stage slices --------------
        if (ks > 0) {
            char* rp = smem + W_BYTES + (ks - 1) * STG_B + mgrp * GRP_B;
#pragma unroll
            for (int mi = 0; mi < 2; mi++)
#pragma unroll
                for (int nf = 0; nf < 4; nf++)
                    *(float4*)(rp + (((mi * 4 + nf) * 32 + lane) << 4)) =
                        *(const float4*)acc[mi][nf];
        }
        bar_named(barid, 128);
        if (ks == 0) {
#pragma unroll
            for (int s = 0; s < 3; s++) {
                const char* rp = smem + W_BYTES + s * STG_B + mgrp * GRP_B;
#pragma unroll
                for (int mi = 0; mi < 2; mi++)
#pragma unroll
                    for (int nf = 0; nf < 4; nf++) {
                        float4 v = *(const float4*)
                            (rp + (((mi * 4 + nf) * 32 + lane) << 4));
                        acc[mi][nf][0] += v.x; acc[mi][nf][1] += v.y;
                        acc[mi][nf][2] += v.z; acc[mi][nf][3] += v.w;
                    }
            }
        }
        bar_named(barid, 128);    // partial-read done: stages reusable at t+1

        // ---------- epilogue (ks0 warp of each m-group) ---------------------
        if (ks == 0) {
            if (t >= 1) {
                if (lane == 0) {
                    unsigned v = __ldcg(&g_ack[t - 1]);
                    while (v < 512u) { __nanosleep(128); v = ld_acq(&g_ack[t - 1]); }
                }
                __syncwarp();
            }
            const char* xps = smem + XP_OFF + mgrp * 4608;
            __half* hw = g_h[wb];
#pragma unroll
            for (int mi = 0; mi < 2; mi++)
#pragma unroll
                for (int nf = 0; nf < 4; nf++)
#pragma unroll
                    for (int h = 0; h < 2; h++) {
                        float v0 = acc[mi][nf][2 * h];
                        float v1 = acc[mi][nf][2 * h + 1];
                        float p0 = __shfl_xor_sync(0xffffffffu, v0, 1);
                        float p1 = __shfl_xor_sync(0xffffffffu, v1, 1);
                        if (writer) {
                            int mr = mi * 16 + h * 8 + q;          // 0..31
                            int m = warp_m + mr;
                            int hcl = nf * 2 + hl;
                            int hc = bidx * 8 + hcl;
                            float4 xv = *(const float4*)
                                (xps + mr * 144 + (nf * 8 + hl * 4) * 4);
                            float ig = sigf(v0 + xv.x);
                            float fg = sigf(v1 + xv.y);
                            float gg = tanhf(p0 + xv.z);
                            float og = sigf(p1 + xv.w);
                            int ci = m * 8 + hcl;
                            float cn = fg * c_s[ci] + ig * gg;
                            c_s[ci] = cn;
                            float hn = og * tanhf(cn);
                            size_t oidx = (size_t)m * HH + hc;
                            out[(size_t)t * BB * HH + oidx] = hn;
                            __stcg(&hw[oidx], __float2half(hn));
                            if (t == TT - 1) {
                                out[OUT_H + oidx] = hn;
                                out[OUT_H + (size_t)BB * HH + oidx] = cn;
                            }
                        }
                    }
            __syncwarp();
            if (lane == 0)
                red_rel(&g_flag[(size_t)t * 64 + (bidx >> 3) * 4 + mgrp]);
        }
    }
}

// ============================================================================
extern "C" void kernel_launch(void* const* d_in, const int* in_sizes, int n_in,
                              void* d_out, int out_size) {
    const float* inputs = (const float*)d_in[0];
    const float* h0     = (const float*)d_in[1];
    const float* c0     = (const float*)d_in[2];
    const float* W_ih   = (const float*)d_in[3];
    const float* W_hh   = (const float*)d_in[4];
    const float* b_ih   = (const float*)d_in[5];
    const float* b_hh   = (const float*)d_in[6];
    float* out = (float*)d_out;

    cudaFuncSetAttribute(lstm_persistent,
                         cudaFuncAttributeMaxDynamicSharedMemorySize, SMEM_TOTAL);

    init_state<<<(BB * HH + 255) / 256, 256>>>(h0);
    wsplit_kernel<<<(int)(((size_t)G4 * HH + 255) / 256), 256>>>(W_hh);

    dim3 xgrid(G4 / 64, (TT * BB) / 64);
    xproj_kernel<<<xgrid, 256>>>(inputs, W_ih, b_ih, b_hh);

    lstm_persistent<<<GRIDN, NTHR, SMEM_TOTAL>>>(out, c0);
}